// round 16
// baseline (speedup 1.0000x reference)
#include <cuda_runtime.h>
#include <cuda_bf16.h>
#include <cstdint>

// Problem constants
#define BQ 4
#define NQ 2048
#define DQ 512
#define PQ 16
#define KQ 4
#define KDQ (KQ*DQ)

// Scratch
__device__ __nv_bfloat16 g_pT_hi[(size_t)BQ*KQ*DQ*NQ];   // [bk][d][j]  (mass folded in)
__device__ __nv_bfloat16 g_pT_lo[(size_t)BQ*KQ*DQ*NQ];
__device__ __nv_bfloat16 g_fh[(size_t)BQ*KQ*NQ*DQ];      // field bf16 hi  [bk][i][d]
__device__ __nv_bfloat16 g_fl[(size_t)BQ*KQ*NQ*DQ];      // field bf16 lo
__device__ __nv_bfloat16 g_cbh[(size_t)DQ*KDQ];          // W_combine hi [dout][kd]
__device__ __nv_bfloat16 g_cbl[(size_t)DQ*KDQ];          // W_combine lo
__device__ __nv_bfloat16 g_wh[(size_t)BQ*KQ*NQ*NQ];      // weights hi [bk][i][j]
__device__ __nv_bfloat16 g_wl[(size_t)BQ*KQ*NQ*NQ];      // weights lo
__device__ __nv_bfloat16 g_chh[(size_t)BQ*NQ*DQ];        // charge hi [b][j][c]
__device__ __nv_bfloat16 g_chl[(size_t)BQ*NQ*DQ];
__device__ __nv_bfloat16 g_cwh[(size_t)KDQ*DQ];          // W_charge hi [kd][c]
__device__ __nv_bfloat16 g_cwl[(size_t)KDQ*DQ];

// ---------------------------------------------------------------------------
// helpers
// ---------------------------------------------------------------------------
__device__ __forceinline__ unsigned smem_u32(const void* p) {
    return (unsigned)__cvta_generic_to_shared(p);
}
__device__ __forceinline__ void cp16(unsigned dst, const void* src) {
    asm volatile("cp.async.cg.shared.global [%0], [%1], 16;" :: "r"(dst), "l"(src));
}
__device__ __forceinline__ void cp_commit() { asm volatile("cp.async.commit_group;"); }
__device__ __forceinline__ void cp_wait0()  { asm volatile("cp.async.wait_group 0;"); }

__device__ __forceinline__ unsigned sw128(unsigned o) {   // SW128: bits[6:4] ^= bits[9:7]
    return o ^ ((o >> 3) & 0x70u);
}
__device__ __forceinline__ unsigned sw64row(unsigned row, unsigned seg) {
    return row*64u + (seg ^ ((row & 6u) << 3));
}

__device__ __forceinline__ void ldmx4(uint32_t* r, unsigned addr) {
    asm volatile("ldmatrix.sync.aligned.m8n8.x4.shared.b16 {%0,%1,%2,%3}, [%4];"
                 : "=r"(r[0]), "=r"(r[1]), "=r"(r[2]), "=r"(r[3]) : "r"(addr));
}

__device__ __forceinline__ void mma_bf16(float* c, const uint32_t* a,
                                         uint32_t b0, uint32_t b1) {
    asm volatile("mma.sync.aligned.m16n8k16.row.col.f32.bf16.bf16.f32 "
                 "{%0,%1,%2,%3}, {%4,%5,%6,%7}, {%8,%9}, {%0,%1,%2,%3};"
                 : "+f"(c[0]), "+f"(c[1]), "+f"(c[2]), "+f"(c[3])
                 : "r"(a[0]), "r"(a[1]), "r"(a[2]), "r"(a[3]), "r"(b0), "r"(b1));
}

__device__ __forceinline__ uint32_t pack_bf2(__nv_bfloat16 a, __nv_bfloat16 b) {
    return (uint32_t)__bfloat16_as_ushort(a) | ((uint32_t)__bfloat16_as_ushort(b) << 16);
}

// proj kernel smem: loop A 2x16KB | B 2x16KB; epilogue reuses as 128x132 fp32
#define PJ_A   0
#define PJ_B   32768
#define SMEM_PJ 67584

// field GEMM smem: 2-stage, A 2x16KB | B 2x16KB
#define FG_A   0
#define FG_B   32768
#define SMEM_FG 65536

// combine kernel smem layout (64-row i-tile)
#define CM_A   0          // 2 x 4KB
#define CM_B   8192       // 2 x 32KB
#define CM_LN  73728      // rowSum 8KB | rowSq 8KB
#define CM_GB  90112      // gamma 2KB | beta 2KB
#define SMEM_COMB 94208

// ---------------------------------------------------------------------------
// Elementwise bf16 hi/lo split kernels
// ---------------------------------------------------------------------------
__global__ __launch_bounds__(256) void split_ch_kernel(const float* __restrict__ src)
{
    const size_t idx = (size_t)blockIdx.x*1024 + threadIdx.x*4;
    float4 v = *(const float4*)(src + idx);
    float vv[4] = {v.x, v.y, v.z, v.w};
#pragma unroll
    for (int q = 0; q < 4; q++) {
        __nv_bfloat16 h = __float2bfloat16(vv[q]);
        g_chh[idx + q] = h;
        g_chl[idx + q] = __float2bfloat16(vv[q] - __bfloat162float(h));
    }
}
__global__ __launch_bounds__(256) void split_cw_kernel(const float* __restrict__ src)
{
    const size_t idx = (size_t)blockIdx.x*1024 + threadIdx.x*4;
    float4 v = *(const float4*)(src + idx);
    float vv[4] = {v.x, v.y, v.z, v.w};
#pragma unroll
    for (int q = 0; q < 4; q++) {
        __nv_bfloat16 h = __float2bfloat16(vv[q]);
        g_cwh[idx + q] = h;
        g_cwl[idx + q] = __float2bfloat16(vv[q] - __bfloat162float(h));
    }
}
__global__ __launch_bounds__(256) void split_cb_kernel(const float* __restrict__ Wcb)
{
    const size_t idx = (size_t)blockIdx.x*1024 + threadIdx.x*4;
    float4 v = *(const float4*)(Wcb + idx);
    float vv[4] = {v.x, v.y, v.z, v.w};
#pragma unroll
    for (int q = 0; q < 4; q++) {
        __nv_bfloat16 h = __float2bfloat16(vv[q]);
        g_cbh[idx + q] = h;
        g_cbl[idx + q] = __float2bfloat16(vv[q] - __bfloat162float(h));
    }
}

// ---------------------------------------------------------------------------
// Kernel A (256 thr / 8 warps 2x4, warp tile 64x32, 2 blocks/SM):
// proj = charge @ Wch^T over 128x128 tile, fused transpose+mass+split epilogue.
// B-frags JIT per n-pair; term-outermost MMA order.
// ---------------------------------------------------------------------------
__global__ __launch_bounds__(256, 2) void proj_mma_kernel(const float* __restrict__ mass)
{
    extern __shared__ char smc[];
    const unsigned sb = smem_u32(smc);
    const int t = threadIdx.x, l = t & 31, w = t >> 5;
    const int wm = w >> 2, wn = w & 3;        // 2x4 warp grid, warp tile 64x32
    const int j0 = blockIdx.x * 128, n0 = blockIdx.y * 128;
    const int b = blockIdx.z;

    __shared__ float massS[128];
    if (t < 128) massS[t] = mass[(size_t)b*NQ + j0 + t];

    const unsigned aRowB = (unsigned)(wm*64 + (l & 15));
    const unsigned aKH   = (unsigned)((l >> 4)*16);
    const unsigned bRowB = (unsigned)((l & 7) + ((l >> 4) & 1)*8);
    const unsigned bKH   = (unsigned)(((l >> 3) & 1)*16);

    float acc[4][4][4];
#pragma unroll
    for (int a = 0; a < 4; a++)
#pragma unroll
        for (int n = 0; n < 4; n++)
#pragma unroll
            for (int q = 0; q < 4; q++) acc[a][n][q] = 0.0f;

    auto loadA = [&](int c, int buf) {        // 128 rows x [hi 64B | lo 64B]
        int row = t >> 1, sel = t & 1;
        const __nv_bfloat16* src = (sel ? g_chl : g_chh) +
            ((size_t)b*NQ + j0 + row)*DQ + c*32;
        unsigned base = (unsigned)(row*128 + sel*64);
        unsigned dst = sb + PJ_A + buf*16384;
#pragma unroll
        for (int cc = 0; cc < 4; cc++)
            cp16(dst + sw128(base + cc*16), (const char*)src + cc*16);
    };
    auto loadB = [&](int c, int buf) {
        int row = t >> 1, sel = t & 1;
        const __nv_bfloat16* src = (sel ? g_cwl : g_cwh) +
            (size_t)(n0 + row)*DQ + c*32;
        unsigned base = (unsigned)(row*128 + sel*64);
        unsigned dst = sb + PJ_B + buf*16384;
#pragma unroll
        for (int cc = 0; cc < 4; cc++)
            cp16(dst + sw128(base + cc*16), (const char*)src + cc*16);
    };

    auto mma_step = [&](int buf, int ks) {
        const unsigned abase = sb + PJ_A + buf*16384;
        const unsigned pbase = sb + PJ_B + buf*16384;
        uint32_t AH[4][4], AL[4][4];
#pragma unroll
        for (int mf = 0; mf < 4; mf++) {
            unsigned o = (aRowB + mf*16)*128 + aKH + ks*32;
            ldmx4(AH[mf], abase + sw128(o));
            ldmx4(AL[mf], abase + sw128(o + 64));
        }
#pragma unroll
        for (int nbp = 0; nbp < 2; nbp++) {
            uint32_t BH[4], BL[4];
            unsigned o = (bRowB + wn*32 + nbp*16)*128 + bKH + ks*32;
            ldmx4(BH, pbase + sw128(o));
            ldmx4(BL, pbase + sw128(o + 64));
            // term-outermost: 8 independent MMAs between accumulator reuses
#pragma unroll
            for (int mf = 0; mf < 4; mf++)
#pragma unroll
                for (int ns = 0; ns < 2; ns++)
                    mma_bf16(acc[mf][nbp*2 + ns], AH[mf], BH[ns*2], BH[ns*2+1]);
#pragma unroll
            for (int mf = 0; mf < 4; mf++)
#pragma unroll
                for (int ns = 0; ns < 2; ns++)
                    mma_bf16(acc[mf][nbp*2 + ns], AH[mf], BL[ns*2], BL[ns*2+1]);
#pragma unroll
            for (int mf = 0; mf < 4; mf++)
#pragma unroll
                for (int ns = 0; ns < 2; ns++)
                    mma_bf16(acc[mf][nbp*2 + ns], AL[mf], BH[ns*2], BH[ns*2+1]);
        }
    };

    loadA(0, 0); loadB(0, 0); cp_commit();
    cp_wait0(); __syncthreads();

    for (int c = 0; c < 16; c++) {
        const int cur = c & 1, nxt = cur ^ 1;
        if (c < 15) { loadA(c+1, nxt); loadB(c+1, nxt); cp_commit(); }
        mma_step(cur, 0);
        mma_step(cur, 1);
        if (c < 15) { cp_wait0(); }
        __syncthreads();
    }

    // ---- fused epilogue: stage transposed fp32 tile, then mass+split+store --
    float* tile = (float*)smc;             // 128 cols x 132 (padded)
#pragma unroll
    for (int mf = 0; mf < 4; mf++)
#pragma unroll
        for (int nf = 0; nf < 4; nf++) {
            const float* cc = acc[mf][nf];
            int jl = wm*64 + mf*16 + (l >> 2);
            int cl = wn*32 + nf*8 + (l & 3)*2;
            tile[(cl  )*132 + jl    ] = cc[0];
            tile[(cl+1)*132 + jl    ] = cc[1];
            tile[(cl  )*132 + jl + 8] = cc[2];
            tile[(cl+1)*132 + jl + 8] = cc[3];
        }
    __syncthreads();

    const int jl = l*4;
    const float4 mv = *(const float4*)&massS[jl];
#pragma unroll
    for (int r = 0; r < 16; r++) {
        int cl = w*16 + r;
        float4 v = *(const float4*)&tile[cl*132 + jl];
        float x0 = v.x*mv.x, x1 = v.y*mv.y, x2 = v.z*mv.z, x3 = v.w*mv.w;
        __nv_bfloat16 h0 = __float2bfloat16(x0), h1 = __float2bfloat16(x1);
        __nv_bfloat16 h2 = __float2bfloat16(x2), h3 = __float2bfloat16(x3);
        __nv_bfloat16 l0 = __float2bfloat16(x0 - __bfloat162float(h0));
        __nv_bfloat16 l1 = __float2bfloat16(x1 - __bfloat162float(h1));
        __nv_bfloat16 l2 = __float2bfloat16(x2 - __bfloat162float(h2));
        __nv_bfloat16 l3 = __float2bfloat16(x3 - __bfloat162float(h3));
        int colG = n0 + cl;
        int k = colG >> 9, d = colG & 511;
        size_t ob = ((size_t)(b*KQ + k)*DQ + d)*NQ + j0 + jl;
        *(uint2*)(g_pT_hi + ob) = make_uint2(pack_bf2(h0, h1), pack_bf2(h2, h3));
        *(uint2*)(g_pT_lo + ob) = make_uint2(pack_bf2(l0, l1), pack_bf2(l2, l3));
    }
}

// ---------------------------------------------------------------------------
// Kernel W: weight generation (equal-bandwidth slices skipped)
// ---------------------------------------------------------------------------
__global__ __launch_bounds__(256) void wgen_kernel(
    const float* __restrict__ position, const float* __restrict__ lbw)
{
    __shared__ float posI[128*16];
    const int b = blockIdx.z, i0 = blockIdx.y*128, j0 = blockIdx.x*128;
    const int t = threadIdx.x;

    for (int u = t; u < 512; u += 256) {
        int r = u >> 2, q = u & 3;
        *(float4*)&posI[r*16 + q*4] =
            *(const float4*)(position + ((size_t)b*NQ + i0 + r)*PQ + q*4);
    }

    float negc[4];
#pragma unroll
    for (int k = 0; k < 4; k++) negc[k] = -1.0f/(2.0f*__expf(lbw[k]) + 1e-8f);
    const bool eq[4] = {false, negc[1] == negc[0], negc[2] == negc[0], negc[3] == negc[0]};

    const int jp = (t & 63)*2;
    const int ig = t >> 6;

    float pj[32];
#pragma unroll
    for (int u2 = 0; u2 < 2; u2++) {
        const float* p = position + ((size_t)b*NQ + j0 + jp + u2)*PQ;
#pragma unroll
        for (int q = 0; q < 16; q += 4) {
            float4 v = *(const float4*)(p + q);
            pj[u2*16+q] = v.x; pj[u2*16+q+1] = v.y;
            pj[u2*16+q+2] = v.z; pj[u2*16+q+3] = v.w;
        }
    }
    __syncthreads();

    for (int ii = 0; ii < 32; ii++) {
        const int i = ig*32 + ii;
        const float* pi = &posI[i*16];
        float d2a = 0.f, d2b = 0.f;
#pragma unroll
        for (int q = 0; q < 16; q++) {
            float piq = pi[q];
            float da = piq - pj[q], db = piq - pj[16+q];
            d2a = fmaf(da, da, d2a); d2b = fmaf(db, db, d2b);
        }
#pragma unroll
        for (int k = 0; k < 4; k++) {
            if (k > 0 && eq[k]) continue;
            float ea = __expf(d2a*negc[k]);
            float eb = __expf(d2b*negc[k]);
            __nv_bfloat162 h2, l2;
            h2.x = __float2bfloat16(ea);
            h2.y = __float2bfloat16(eb);
            l2.x = __float2bfloat16(ea - __bfloat162float(h2.x));
            l2.y = __float2bfloat16(eb - __bfloat162float(h2.y));
            size_t off = ((size_t)(b*KQ + k)*NQ + i0 + i)*NQ + j0 + jp;
            *(__nv_bfloat162*)(g_wh + off) = h2;
            *(__nv_bfloat162*)(g_wl + off) = l2;
        }
    }
}

// ---------------------------------------------------------------------------
// Kernel B (256 thr / 8 warps 2x4, warp tile 64x32, 2 blocks/SM):
// field GEMM over 128x128 tile, K=2048 in 64 chunks, 2-stage.
// A-base folds equal-bandwidth k to slice 0. JIT B-frags, term-outermost.
// ---------------------------------------------------------------------------
__global__ __launch_bounds__(256, 2) void field_gemm_kernel(const float* __restrict__ lbw)
{
    extern __shared__ char smc[];
    const unsigned sb = smem_u32(smc);
    const int t = threadIdx.x, l = t & 31, w = t >> 5;
    const int wm = w >> 2, wn = w & 3;
    const int i0 = blockIdx.x * 128, d0 = blockIdx.y * 128;
    const int bk = blockIdx.z, b = bk >> 2, k = bk & 3;

    const float nc0 = -1.0f/(2.0f*__expf(lbw[0]) + 1e-8f);
    const float nck = -1.0f/(2.0f*__expf(lbw[k]) + 1e-8f);
    const int ksrc = (nck == nc0) ? 0 : k;
    const size_t wbase_g = (size_t)(b*KQ + ksrc)*NQ*NQ;

    const unsigned aRowB = (unsigned)(wm*64 + (l & 15));
    const unsigned aKH   = (unsigned)((l >> 4)*16);
    const unsigned bRowB = (unsigned)((l & 7) + ((l >> 4) & 1)*8);
    const unsigned bKH   = (unsigned)(((l >> 3) & 1)*16);

    float acc[4][4][4];
#pragma unroll
    for (int a = 0; a < 4; a++)
#pragma unroll
        for (int n = 0; n < 4; n++)
#pragma unroll
            for (int q = 0; q < 4; q++) acc[a][n][q] = 0.0f;

    auto loadA = [&](int c, int buf) {
        int row = t >> 1, sel = t & 1;
        const __nv_bfloat16* src = (sel ? g_wl : g_wh) +
            wbase_g + (size_t)(i0 + row)*NQ + c*32;
        unsigned base = (unsigned)(row*128 + sel*64);
        unsigned dst = sb + FG_A + buf*16384;
#pragma unroll
        for (int cc = 0; cc < 4; cc++)
            cp16(dst + sw128(base + cc*16), (const char*)src + cc*16);
    };
    auto loadB = [&](int c, int buf) {
        int row = t >> 1, sel = t & 1;
        const __nv_bfloat16* src = (sel ? g_pT_lo : g_pT_hi) +
            ((size_t)bk*DQ + d0 + row)*NQ + c*32;
        unsigned base = (unsigned)(row*128 + sel*64);
        unsigned dst = sb + FG_B + buf*16384;
#pragma unroll
        for (int cc = 0; cc < 4; cc++)
            cp16(dst + sw128(base + cc*16), (const char*)src + cc*16);
    };

    auto mma_step = [&](int buf, int ks) {
        const unsigned abase = sb + FG_A + buf*16384;
        const unsigned pbase = sb + FG_B + buf*16384;
        uint32_t AH[4][4], AL[4][4];
#pragma unroll
        for (int mf = 0; mf < 4; mf++) {
            unsigned o = (aRowB + mf*16)*128 + aKH + ks*32;
            ldmx4(AH[mf], abase + sw128(o));
            ldmx4(AL[mf], abase + sw128(o + 64));
        }
#pragma unroll
        for (int nbp = 0; nbp < 2; nbp++) {
            uint32_t BH[4], BL[4];
            unsigned o = (bRowB + wn*32 + nbp*16)*128 + bKH + ks*32;
            ldmx4(BH, pbase + sw128(o));
            ldmx4(BL, pbase + sw128(o + 64));
#pragma unroll
            for (int mf = 0; mf < 4; mf++)
#pragma unroll
                for (int ns = 0; ns < 2; ns++)
                    mma_bf16(acc[mf][nbp*2 + ns], AH[mf], BH[ns*2], BH[ns*2+1]);
#pragma unroll
            for (int mf = 0; mf < 4; mf++)
#pragma unroll
                for (int ns = 0; ns < 2; ns++)
                    mma_bf16(acc[mf][nbp*2 + ns], AH[mf], BL[ns*2], BL[ns*2+1]);
#pragma unroll
            for (int mf = 0; mf < 4; mf++)
#pragma unroll
                for (int ns = 0; ns < 2; ns++)
                    mma_bf16(acc[mf][nbp*2 + ns], AL[mf], BH[ns*2], BH[ns*2+1]);
        }
    };

    loadA(0, 0); loadB(0, 0); cp_commit();
    cp_wait0(); __syncthreads();

    for (int c = 0; c < 64; c++) {
        const int cur = c & 1, nxt = cur ^ 1;
        if (c < 63) { loadA(c+1, nxt); loadB(c+1, nxt); cp_commit(); }
        mma_step(cur, 0);
        mma_step(cur, 1);
        if (c < 63) { cp_wait0(); }
        __syncthreads();
    }

    // epilogue: write bf16 hi/lo split of field
#pragma unroll
    for (int mf = 0; mf < 4; mf++)
#pragma unroll
        for (int nf = 0; nf < 4; nf++) {
            const float* cc = acc[mf][nf];
            int i = i0 + wm*64 + mf*16 + (l >> 2);
            int d = d0 + wn*32 + nf*8 + (l & 3)*2;
            size_t o1 = ((size_t)bk*NQ + i)*DQ + d;
            size_t o2 = o1 + (size_t)8*DQ;
            __nv_bfloat162 h2, l2;
            h2.x = __float2bfloat16(cc[0]); h2.y = __float2bfloat16(cc[1]);
            l2.x = __float2bfloat16(cc[0] - __bfloat162float(h2.x));
            l2.y = __float2bfloat16(cc[1] - __bfloat162float(h2.y));
            *(__nv_bfloat162*)(g_fh + o1) = h2;
            *(__nv_bfloat162*)(g_fl + o1) = l2;
            h2.x = __float2bfloat16(cc[2]); h2.y = __float2bfloat16(cc[3]);
            l2.x = __float2bfloat16(cc[2] - __bfloat162float(h2.x));
            l2.y = __float2bfloat16(cc[3] - __bfloat162float(h2.y));
            *(__nv_bfloat162*)(g_fh + o2) = h2;
            *(__nv_bfloat162*)(g_fl + o2) = l2;
        }
}

// ---------------------------------------------------------------------------
// Kernel C (256 thr, 64-row i-tile): combine + LN (unchanged from R14)
// ---------------------------------------------------------------------------
__global__ __launch_bounds__(256, 1) void combine_mma_kernel(
    const float* __restrict__ gammaP, const float* __restrict__ betaP,
    float* __restrict__ out)
{
    extern __shared__ char smc[];
    const unsigned sb = smem_u32(smc);
    const int t = threadIdx.x, l = t & 31, w = t >> 5;
    const int i0 = blockIdx.x * 64;
    const int b  = blockIdx.y;

    float* rowSum = (float*)(smc + CM_LN);          // 64 x 32
    float* rowSq  = rowSum + 2048;
    float* gammaS = (float*)(smc + CM_GB);
    float* betaS  = gammaS + 512;
    __shared__ float meanS[64], rsS[64];

    for (int u = t; u < 512; u += 256) { gammaS[u] = gammaP[u]; betaS[u] = betaP[u]; }

    float acc[4][8][4];
#pragma unroll
    for (int mf = 0; mf < 4; mf++)
#pragma unroll
        for (int nf = 0; nf < 8; nf++)
#pragma unroll
            for (int q = 0; q < 4; q++) acc[mf][nf][q] = 0.0f;

    auto loadA = [&](int c, int buf) {
        int row = t >> 2, s = t & 3, sel = s >> 1, h = s & 1;
        int k = c >> 5, d0 = (c & 31)*16;
        const __nv_bfloat16* src = (sel ? g_fl : g_fh) +
            ((size_t)(b*KQ + k)*NQ + i0 + row)*DQ + d0 + h*8;
        cp16(sb + CM_A + buf*4096 + sw64row(row, sel*32 + h*16), src);
    };
    auto loadB = [&](int c, int buf) {
        unsigned dst = sb + CM_B + buf*32768;
#pragma unroll
        for (int rr = 0; rr < 2; rr++) {
            int row = t*2 + rr;
            const __nv_bfloat16* srcH = g_cbh + (size_t)row*KDQ + c*16;
            const __nv_bfloat16* srcL = g_cbl + (size_t)row*KDQ + c*16;
            cp16(dst + sw64row(row, 0),  srcH);
            cp16(dst + sw64row(row, 16), srcH + 8);
            cp16(dst + sw64row(row, 32), srcL);
            cp16(dst + sw64row(row, 48), srcL + 8);
        }
    };

    const unsigned aRow = (unsigned)(l & 15);
    const unsigned aH   = (unsigned)((l >> 4)*16);
    const unsigned bRow = (unsigned)((l & 7) + ((l >> 4) & 1)*8);
    const unsigned bH   = (unsigned)(((l >> 3) & 1)*16);

    loadA(0, 0); loadB(0, 0); cp_commit();
    cp_wait0(); __syncthreads();

    for (int c = 0; c < 128; c++) {
        const int cur = c & 1, nxt = cur ^ 1;
        if (c + 1 < 128) { loadA(c+1, nxt); loadB(c+1, nxt); }
        cp_commit();

        const unsigned abase = sb + CM_A + cur*4096;
        const unsigned bbase = sb + CM_B + cur*32768;
        uint32_t AH[4][4], AL[4][4];
#pragma unroll
        for (int mf = 0; mf < 4; mf++) {
            unsigned r = mf*16 + aRow;
            ldmx4(AH[mf], abase + sw64row(r, aH));
            ldmx4(AL[mf], abase + sw64row(r, 32 + aH));
        }
#pragma unroll
        for (int nb = 0; nb < 4; nb++) {
            uint32_t BH[4], BL[4];
            unsigned r = w*64 + nb*16 + bRow;
            ldmx4(BH, bbase + sw64row(r, bH));
            ldmx4(BL, bbase + sw64row(r, 32 + bH));
#pragma unroll
            for (int mf = 0; mf < 4; mf++)
#pragma unroll
                for (int ns = 0; ns < 2; ns++)
                    mma_bf16(acc[mf][nb*2 + ns], AH[mf], BH[ns*2], BH[ns*2+1]);
#pragma unroll
            for (int mf = 0; mf < 4; mf++)
#pragma unroll
                for (int ns = 0; ns < 2; ns++)
                    mma_bf16(acc[mf][nb*2 + ns], AH[mf], BL[ns*2], BL[ns*2+1]);
#pragma unroll
            for (int mf = 0; mf < 4; mf++)
#pragma unroll
                for (int ns = 0; ns < 2; ns++)
                    mma_bf16(acc[mf][nb*2 + ns], AL[mf], BH[ns*2], BH[ns*2+1]);
        }

        if (c + 1 < 128) { cp_wait0(); }
        __syncthreads();
    }

    // ---- LayerNorm over 64 rows ----
    const int cw = w*4 + (l & 3);
#pragma unroll
    for (int mf = 0; mf < 4; mf++) {
        float sLo = 0.f, sHi = 0.f, qLo = 0.f, qHi = 0.f;
#pragma unroll
        for (int nf = 0; nf < 8; nf++) {
            const float* cc = acc[mf][nf];
            sLo += cc[0] + cc[1];  qLo += cc[0]*cc[0] + cc[1]*cc[1];
            sHi += cc[2] + cc[3];  qHi += cc[2]*cc[2] + cc[3]*cc[3];
        }
        int rLo = mf*16 + (l >> 2), rHi = rLo + 8;
        rowSum[rLo*32 + cw] = sLo;  rowSq[rLo*32 + cw] = qLo;
        rowSum[rHi*32 + cw] = sHi;  rowSq[rHi*32 + cw] = qHi;
    }
    __syncthreads();
#pragma unroll
    for (int rr = 0; rr < 8; rr++) {
        int row = w*8 + rr;
        float s  = rowSum[row*32 + l];
        float s2 = rowSq [row*32 + l];
#pragma unroll
        for (int off = 16; off > 0; off >>= 1) {
            s  += __shfl_xor_sync(0xffffffffu, s,  off);
            s2 += __shfl_xor_sync(0xffffffffu, s2, off);
        }
        if (l == 0) {
            float mean = s * (1.0f/512.0f);
            float var  = s2 * (1.0f/512.0f) - mean*mean;
            meanS[row] = mean;
            rsS[row]   = rsqrtf(var + 1e-5f);
        }
    }
    __syncthreads();

#pragma unroll
    for (int mf = 0; mf < 4; mf++)
#pragma unroll
        for (int nf = 0; nf < 8; nf++) {
            const float* cc = acc[mf][nf];
            int dout = w*64 + nf*8 + (l & 3)*2;
            float g0 = gammaS[dout], g1 = gammaS[dout+1];
            float b0 = betaS[dout],  b1 = betaS[dout+1];
            int rLo = mf*16 + (l >> 2), rHi = rLo + 8;
            float mLo = meanS[rLo], rsLo = rsS[rLo];
            float mHi = meanS[rHi], rsHi = rsS[rHi];
            float* dLo = out + ((size_t)b*NQ + i0 + rLo)*DQ + dout;
            float* dHi = out + ((size_t)b*NQ + i0 + rHi)*DQ + dout;
            *(float2*)dLo = make_float2((cc[0]-mLo)*rsLo*g0 + b0,
                                        (cc[1]-mLo)*rsLo*g1 + b1);
            *(float2*)dHi = make_float2((cc[2]-mHi)*rsHi*g0 + b0,
                                        (cc[3]-mHi)*rsHi*g1 + b1);
        }
}

// ---------------------------------------------------------------------------
extern "C" void kernel_launch(void* const* d_in, const int* in_sizes, int n_in,
                              void* d_out, int out_size)
{
    const float* charge   = (const float*)d_in[0];
    const float* position = (const float*)d_in[1];
    const float* mass     = (const float*)d_in[2];
    const float* lbw      = (const float*)d_in[3];
    const float* Wch      = (const float*)d_in[4];
    const float* Wcb      = (const float*)d_in[5];
    const float* gammaP   = (const float*)d_in[6];
    const float* betaP    = (const float*)d_in[7];
    float* out = (float*)d_out;

    // One-time resource setup (first, non-captured, correctness call).
    static cudaStream_t s1 = nullptr;
    static cudaEvent_t evFork = nullptr, evJoin = nullptr;
    if (!s1) {
        cudaStreamCreateWithFlags(&s1, cudaStreamNonBlocking);
        cudaEventCreateWithFlags(&evFork, cudaEventDisableTiming);
        cudaEventCreateWithFlags(&evJoin, cudaEventDisableTiming);
        cudaFuncSetAttribute(proj_mma_kernel,
                             cudaFuncAttributeMaxDynamicSharedMemorySize, SMEM_PJ);
        cudaFuncSetAttribute(field_gemm_kernel,
                             cudaFuncAttributeMaxDynamicSharedMemorySize, SMEM_FG);
        cudaFuncSetAttribute(combine_mma_kernel,
                             cudaFuncAttributeMaxDynamicSharedMemorySize, SMEM_COMB);
    }

    // Fork: side stream runs wgen + split_cb (independent of proj chain)
    cudaEventRecord(evFork, 0);
    cudaStreamWaitEvent(s1, evFork, 0);
    split_cb_kernel  <<<(DQ*KDQ)/1024, 256, 0, s1>>>(Wcb);
    wgen_kernel      <<<dim3(NQ/128, NQ/128, BQ), 256, 0, s1>>>(position, lbw);
    cudaEventRecord(evJoin, s1);

    // Main chain on default stream
    split_ch_kernel  <<<(BQ*NQ*DQ)/1024, 256>>>(charge);
    split_cw_kernel  <<<(KDQ*DQ)/1024, 256>>>(Wch);
    proj_mma_kernel  <<<dim3(NQ/128, KDQ/128, BQ), 256, SMEM_PJ>>>(mass);

    // Join: field needs wgen output
    cudaStreamWaitEvent(0, evJoin, 0);
    field_gemm_kernel<<<dim3(NQ/128, DQ/128, BQ*KQ), 256, SMEM_FG>>>(lbw);
    combine_mma_kernel<<<dim3(NQ/64, BQ), 256, SMEM_COMB>>>(gammaP, betaP, out);
}

// round 17
// speedup vs baseline: 2.4316x; 2.4316x over previous
#include <cuda_runtime.h>
#include <cuda_bf16.h>
#include <cstdint>

// Problem constants
#define BQ 4
#define NQ 2048
#define DQ 512
#define PQ 16
#define KQ 4
#define KDQ (KQ*DQ)

// Scratch
__device__ __nv_bfloat16 g_fh[(size_t)BQ*KQ*NQ*DQ];      // T hi  [bk][i][c]
__device__ __nv_bfloat16 g_fl[(size_t)BQ*KQ*NQ*DQ];      // T lo
__device__ __nv_bfloat16 g_cbh[(size_t)DQ*KDQ];          // W_combine hi [e][kd]
__device__ __nv_bfloat16 g_cbl[(size_t)DQ*KDQ];          // W_combine lo
__device__ __nv_bfloat16 g_wh[(size_t)BQ*KQ*NQ*NQ];      // weights hi [bk][i][j]
__device__ __nv_bfloat16 g_wl[(size_t)BQ*KQ*NQ*NQ];      // weights lo
__device__ __nv_bfloat16 g_mcT_h[(size_t)BQ*DQ*NQ];      // (mass*charge)^T hi [b][c][j]
__device__ __nv_bfloat16 g_mcT_l[(size_t)BQ*DQ*NQ];
__device__ __nv_bfloat16 g_cwT_h[(size_t)DQ*KDQ];        // Wch^T hi [c][kd]
__device__ __nv_bfloat16 g_cwT_l[(size_t)DQ*KDQ];
__device__ __nv_bfloat16 g_mkh[(size_t)KQ*DQ*DQ];        // M_k hi [k][e][c]
__device__ __nv_bfloat16 g_mkl[(size_t)KQ*DQ*DQ];

// ---------------------------------------------------------------------------
// helpers
// ---------------------------------------------------------------------------
__device__ __forceinline__ unsigned smem_u32(const void* p) {
    return (unsigned)__cvta_generic_to_shared(p);
}
__device__ __forceinline__ void cp16(unsigned dst, const void* src) {
    asm volatile("cp.async.cg.shared.global [%0], [%1], 16;" :: "r"(dst), "l"(src));
}
__device__ __forceinline__ void cp_commit() { asm volatile("cp.async.commit_group;"); }
__device__ __forceinline__ void cp_wait0()  { asm volatile("cp.async.wait_group 0;"); }

__device__ __forceinline__ unsigned sw128(unsigned o) {
    return o ^ ((o >> 3) & 0x70u);
}
__device__ __forceinline__ unsigned sw64row(unsigned row, unsigned seg) {
    return row*64u + (seg ^ ((row & 6u) << 3));
}

__device__ __forceinline__ void ldmx4(uint32_t* r, unsigned addr) {
    asm volatile("ldmatrix.sync.aligned.m8n8.x4.shared.b16 {%0,%1,%2,%3}, [%4];"
                 : "=r"(r[0]), "=r"(r[1]), "=r"(r[2]), "=r"(r[3]) : "r"(addr));
}

__device__ __forceinline__ void mma_bf16(float* c, const uint32_t* a,
                                         uint32_t b0, uint32_t b1) {
    asm volatile("mma.sync.aligned.m16n8k16.row.col.f32.bf16.bf16.f32 "
                 "{%0,%1,%2,%3}, {%4,%5,%6,%7}, {%8,%9}, {%0,%1,%2,%3};"
                 : "+f"(c[0]), "+f"(c[1]), "+f"(c[2]), "+f"(c[3])
                 : "r"(a[0]), "r"(a[1]), "r"(a[2]), "r"(a[3]), "r"(b0), "r"(b1));
}

__device__ __forceinline__ uint32_t pack_bf2(__nv_bfloat16 a, __nv_bfloat16 b) {
    return (uint32_t)__bfloat16_as_ushort(a) | ((uint32_t)__bfloat16_as_ushort(b) << 16);
}

// shared GEMM smem: 2-stage, A 2x16KB | B 2x16KB
#define FG_A   0
#define FG_B   32768
#define SMEM_FG 65536

// out kernel smem layout (64-row i-tile)
#define CM_A   0          // 2 x 4KB
#define CM_B   8192       // 2 x 32KB
#define CM_LN  73728      // rowSum 8KB | rowSq 8KB
#define CM_GB  90112      // gamma 2KB | beta 2KB
#define SMEM_COMB 94208

// ---------------------------------------------------------------------------
// split/transpose kernels
// ---------------------------------------------------------------------------
__global__ __launch_bounds__(256) void split_mct_kernel(
    const float* __restrict__ charge, const float* __restrict__ mass)
{
    __shared__ float tile[32][33];
    const int b = blockIdx.z;
    const int j0 = blockIdx.x * 32, c0 = blockIdx.y * 32;
    const int tx = threadIdx.x & 31, ty = threadIdx.x >> 5;
    const float* src = charge + ((size_t)b*NQ + j0)*DQ + c0;
#pragma unroll
    for (int r = 0; r < 4; r++)
        tile[r*8+ty][tx] = src[(size_t)(r*8+ty)*DQ + tx];
    __syncthreads();
    const float mj = mass[(size_t)b*NQ + j0 + tx];
    const size_t ob = ((size_t)b*DQ + c0)*NQ + j0;
#pragma unroll
    for (int r = 0; r < 4; r++) {
        int c = r*8 + ty;
        float v = tile[tx][c] * mj;
        __nv_bfloat16 h = __float2bfloat16(v);
        __nv_bfloat16 l = __float2bfloat16(v - __bfloat162float(h));
        g_mcT_h[ob + (size_t)c*NQ + tx] = h;
        g_mcT_l[ob + (size_t)c*NQ + tx] = l;
    }
}

__global__ __launch_bounds__(256) void split_cwt_kernel(const float* __restrict__ Wch)
{
    __shared__ float tile[32][33];
    const int kd0 = blockIdx.x * 32, c0 = blockIdx.y * 32;
    const int tx = threadIdx.x & 31, ty = threadIdx.x >> 5;
    const float* src = Wch + (size_t)kd0*DQ + c0;
#pragma unroll
    for (int r = 0; r < 4; r++)
        tile[r*8+ty][tx] = src[(size_t)(r*8+ty)*DQ + tx];   // tile[kd_l][c_l]
    __syncthreads();
#pragma unroll
    for (int r = 0; r < 4; r++) {
        int c = r*8 + ty;
        float v = tile[tx][c];
        __nv_bfloat16 h = __float2bfloat16(v);
        __nv_bfloat16 l = __float2bfloat16(v - __bfloat162float(h));
        g_cwT_h[(size_t)(c0 + c)*KDQ + kd0 + tx] = h;
        g_cwT_l[(size_t)(c0 + c)*KDQ + kd0 + tx] = l;
    }
}

__global__ __launch_bounds__(256) void split_cb_kernel(const float* __restrict__ Wcb)
{
    const size_t idx = (size_t)blockIdx.x*1024 + threadIdx.x*4;
    float4 v = *(const float4*)(Wcb + idx);
    float vv[4] = {v.x, v.y, v.z, v.w};
#pragma unroll
    for (int q = 0; q < 4; q++) {
        __nv_bfloat16 h = __float2bfloat16(vv[q]);
        g_cbh[idx + q] = h;
        g_cbl[idx + q] = __float2bfloat16(vv[q] - __bfloat162float(h));
    }
}

// ---------------------------------------------------------------------------
// Kernel M: M_k[e][c] = sum_d Wcb[e, k*512+d] * Wch[k*512+d, c]
// ---------------------------------------------------------------------------
__global__ __launch_bounds__(512, 1) void mk_build_kernel()
{
    extern __shared__ char smc[];
    const unsigned sb = smem_u32(smc);
    const int t = threadIdx.x, l = t & 31, w = t >> 5;
    const int wm = w & 3, wn = w >> 2;
    const int e0 = blockIdx.x * 128, c0 = blockIdx.y * 128;
    const int kz = blockIdx.z;
    const size_t kbase = (size_t)kz * 512;

    const unsigned aRowB = (unsigned)(wm*32 + (l & 15));
    const unsigned aKH   = (unsigned)((l >> 4)*16);
    const unsigned bRowB = (unsigned)((l & 7) + ((l >> 4) & 1)*8);
    const unsigned bKH   = (unsigned)(((l >> 3) & 1)*16);

    float acc[2][4][4];
#pragma unroll
    for (int a = 0; a < 2; a++)
#pragma unroll
        for (int n = 0; n < 4; n++)
#pragma unroll
            for (int q = 0; q < 4; q++) acc[a][n][q] = 0.0f;

    auto loadA = [&](int c, int buf) {
        int row = t >> 2, s = t & 3, sel = s >> 1, h = s & 1;
        const __nv_bfloat16* src = (sel ? g_cbl : g_cbh) +
            (size_t)(e0 + row)*KDQ + kbase + c*32 + h*16;
        unsigned base = (unsigned)(row*128 + s*32);
        unsigned dst = sb + FG_A + buf*16384;
        cp16(dst + sw128(base),      src);
        cp16(dst + sw128(base + 16), src + 8);
    };
    auto loadB = [&](int c, int buf) {
        int row = t >> 2, s = t & 3, sel = s >> 1, h = s & 1;
        const __nv_bfloat16* src = (sel ? g_cwT_l : g_cwT_h) +
            (size_t)(c0 + row)*KDQ + kbase + c*32 + h*16;
        unsigned base = (unsigned)(row*128 + s*32);
        unsigned dst = sb + FG_B + buf*16384;
        cp16(dst + sw128(base),      src);
        cp16(dst + sw128(base + 16), src + 8);
    };

    auto mma_step = [&](int buf, int ks) {
        const unsigned abase = sb + FG_A + buf*16384;
        const unsigned pbase = sb + FG_B + buf*16384;
        uint32_t AH[2][4], AL[2][4], BH[2][4], BL[2][4];
#pragma unroll
        for (int mf = 0; mf < 2; mf++) {
            unsigned o = (aRowB + mf*16)*128 + aKH + ks*32;
            ldmx4(AH[mf], abase + sw128(o));
            ldmx4(AL[mf], abase + sw128(o + 64));
        }
#pragma unroll
        for (int nb = 0; nb < 2; nb++) {
            unsigned o = (bRowB + wn*32 + nb*16)*128 + bKH + ks*32;
            ldmx4(BH[nb], pbase + sw128(o));
            ldmx4(BL[nb], pbase + sw128(o + 64));
        }
#pragma unroll
        for (int mf = 0; mf < 2; mf++)
#pragma unroll
            for (int nb = 0; nb < 2; nb++)
#pragma unroll
                for (int ns = 0; ns < 2; ns++)
                    mma_bf16(acc[mf][nb*2 + ns], AH[mf], BH[nb][ns*2], BH[nb][ns*2+1]);
#pragma unroll
        for (int mf = 0; mf < 2; mf++)
#pragma unroll
            for (int nb = 0; nb < 2; nb++)
#pragma unroll
                for (int ns = 0; ns < 2; ns++)
                    mma_bf16(acc[mf][nb*2 + ns], AH[mf], BL[nb][ns*2], BL[nb][ns*2+1]);
#pragma unroll
        for (int mf = 0; mf < 2; mf++)
#pragma unroll
            for (int nb = 0; nb < 2; nb++)
#pragma unroll
                for (int ns = 0; ns < 2; ns++)
                    mma_bf16(acc[mf][nb*2 + ns], AL[mf], BH[nb][ns*2], BH[nb][ns*2+1]);
    };

    loadA(0, 0); loadB(0, 0); cp_commit();
    cp_wait0(); __syncthreads();

    for (int c = 0; c < 16; c++) {
        const int cur = c & 1, nxt = cur ^ 1;
        if (c < 15) { loadA(c+1, nxt); loadB(c+1, nxt); cp_commit(); }
        mma_step(cur, 0);
        mma_step(cur, 1);
        if (c < 15) { cp_wait0(); }
        __syncthreads();
    }

#pragma unroll
    for (int mf = 0; mf < 2; mf++)
#pragma unroll
        for (int nf = 0; nf < 4; nf++) {
            const float* cc = acc[mf][nf];
            int e = e0 + wm*32 + mf*16 + (l >> 2);
            int c = c0 + wn*32 + nf*8 + (l & 3)*2;
            size_t o1 = ((size_t)kz*512 + e)*512 + c;
            size_t o2 = o1 + (size_t)8*512;
            __nv_bfloat162 h2, l2;
            h2.x = __float2bfloat16(cc[0]); h2.y = __float2bfloat16(cc[1]);
            l2.x = __float2bfloat16(cc[0] - __bfloat162float(h2.x));
            l2.y = __float2bfloat16(cc[1] - __bfloat162float(h2.y));
            *(__nv_bfloat162*)(g_mkh + o1) = h2;
            *(__nv_bfloat162*)(g_mkl + o1) = l2;
            h2.x = __float2bfloat16(cc[2]); h2.y = __float2bfloat16(cc[3]);
            l2.x = __float2bfloat16(cc[2] - __bfloat162float(h2.x));
            l2.y = __float2bfloat16(cc[3] - __bfloat162float(h2.y));
            *(__nv_bfloat162*)(g_mkh + o2) = h2;
            *(__nv_bfloat162*)(g_mkl + o2) = l2;
        }
}

// ---------------------------------------------------------------------------
// Kernel W: weight generation (equal-bandwidth slices skipped)
// ---------------------------------------------------------------------------
__global__ __launch_bounds__(256) void wgen_kernel(
    const float* __restrict__ position, const float* __restrict__ lbw)
{
    __shared__ float posI[128*16];
    const int b = blockIdx.z, i0 = blockIdx.y*128, j0 = blockIdx.x*128;
    const int t = threadIdx.x;

    for (int u = t; u < 512; u += 256) {
        int r = u >> 2, q = u & 3;
        *(float4*)&posI[r*16 + q*4] =
            *(const float4*)(position + ((size_t)b*NQ + i0 + r)*PQ + q*4);
    }

    float negc[4];
#pragma unroll
    for (int k = 0; k < 4; k++) negc[k] = -1.0f/(2.0f*__expf(lbw[k]) + 1e-8f);
    const bool eq[4] = {false, negc[1] == negc[0], negc[2] == negc[0], negc[3] == negc[0]};

    const int jp = (t & 63)*2;
    const int ig = t >> 6;

    float pj[32];
#pragma unroll
    for (int u2 = 0; u2 < 2; u2++) {
        const float* p = position + ((size_t)b*NQ + j0 + jp + u2)*PQ;
#pragma unroll
        for (int q = 0; q < 16; q += 4) {
            float4 v = *(const float4*)(p + q);
            pj[u2*16+q] = v.x; pj[u2*16+q+1] = v.y;
            pj[u2*16+q+2] = v.z; pj[u2*16+q+3] = v.w;
        }
    }
    __syncthreads();

    for (int ii = 0; ii < 32; ii++) {
        const int i = ig*32 + ii;
        const float* pi = &posI[i*16];
        float d2a = 0.f, d2b = 0.f;
#pragma unroll
        for (int q = 0; q < 16; q++) {
            float piq = pi[q];
            float da = piq - pj[q], db = piq - pj[16+q];
            d2a = fmaf(da, da, d2a); d2b = fmaf(db, db, d2b);
        }
#pragma unroll
        for (int k = 0; k < 4; k++) {
            if (k > 0 && eq[k]) continue;
            float ea = __expf(d2a*negc[k]);
            float eb = __expf(d2b*negc[k]);
            __nv_bfloat162 h2, l2;
            h2.x = __float2bfloat16(ea);
            h2.y = __float2bfloat16(eb);
            l2.x = __float2bfloat16(ea - __bfloat162float(h2.x));
            l2.y = __float2bfloat16(eb - __bfloat162float(h2.y));
            size_t off = ((size_t)(b*KQ + k)*NQ + i0 + i)*NQ + j0 + jp;
            *(__nv_bfloat162*)(g_wh + off) = h2;
            *(__nv_bfloat162*)(g_wl + off) = l2;
        }
    }
}

// ---------------------------------------------------------------------------
// Kernel T (512 thr / 16 warps 4x4): T[bk][i][c] = sum_j W[bk][i][j]*mcT[b][c][j]
// Folded k-slots exit immediately (never read downstream).
// ---------------------------------------------------------------------------
__global__ __launch_bounds__(512, 1) void t_gemm_kernel(const float* __restrict__ lbw)
{
    const int bk = blockIdx.z, b = bk >> 2, k = bk & 3;
    {
        const float nc0 = -1.0f/(2.0f*__expf(lbw[0]) + 1e-8f);
        const float nck = -1.0f/(2.0f*__expf(lbw[k]) + 1e-8f);
        if (k > 0 && nck == nc0) return;
    }

    extern __shared__ char smc[];
    const unsigned sb = smem_u32(smc);
    const int t = threadIdx.x, l = t & 31, w = t >> 5;
    const int wm = w & 3, wn = w >> 2;
    const int i0 = blockIdx.x * 128, c0t = blockIdx.y * 128;

    const unsigned aRowB = (unsigned)(wm*32 + (l & 15));
    const unsigned aKH   = (unsigned)((l >> 4)*16);
    const unsigned bRowB = (unsigned)((l & 7) + ((l >> 4) & 1)*8);
    const unsigned bKH   = (unsigned)(((l >> 3) & 1)*16);

    float acc[2][4][4];
#pragma unroll
    for (int a = 0; a < 2; a++)
#pragma unroll
        for (int n = 0; n < 4; n++)
#pragma unroll
            for (int q = 0; q < 4; q++) acc[a][n][q] = 0.0f;

    auto loadA = [&](int c, int buf) {
        int row = t >> 2, s = t & 3, sel = s >> 1, h = s & 1;
        const __nv_bfloat16* src = (sel ? g_wl : g_wh) +
            (size_t)bk*NQ*NQ + (size_t)(i0 + row)*NQ + c*32 + h*16;
        unsigned base = (unsigned)(row*128 + s*32);
        unsigned dst = sb + FG_A + buf*16384;
        cp16(dst + sw128(base),      src);
        cp16(dst + sw128(base + 16), src + 8);
    };
    auto loadB = [&](int c, int buf) {
        int row = t >> 2, s = t & 3, sel = s >> 1, h = s & 1;
        const __nv_bfloat16* src = (sel ? g_mcT_l : g_mcT_h) +
            ((size_t)b*DQ + c0t + row)*NQ + c*32 + h*16;
        unsigned base = (unsigned)(row*128 + s*32);
        unsigned dst = sb + FG_B + buf*16384;
        cp16(dst + sw128(base),      src);
        cp16(dst + sw128(base + 16), src + 8);
    };

    auto mma_step = [&](int buf, int ks) {
        const unsigned abase = sb + FG_A + buf*16384;
        const unsigned pbase = sb + FG_B + buf*16384;
        uint32_t AH[2][4], AL[2][4], BH[2][4], BL[2][4];
#pragma unroll
        for (int mf = 0; mf < 2; mf++) {
            unsigned o = (aRowB + mf*16)*128 + aKH + ks*32;
            ldmx4(AH[mf], abase + sw128(o));
            ldmx4(AL[mf], abase + sw128(o + 64));
        }
#pragma unroll
        for (int nb = 0; nb < 2; nb++) {
            unsigned o = (bRowB + wn*32 + nb*16)*128 + bKH + ks*32;
            ldmx4(BH[nb], pbase + sw128(o));
            ldmx4(BL[nb], pbase + sw128(o + 64));
        }
#pragma unroll
        for (int mf = 0; mf < 2; mf++)
#pragma unroll
            for (int nb = 0; nb < 2; nb++)
#pragma unroll
                for (int ns = 0; ns < 2; ns++)
                    mma_bf16(acc[mf][nb*2 + ns], AH[mf], BH[nb][ns*2], BH[nb][ns*2+1]);
#pragma unroll
        for (int mf = 0; mf < 2; mf++)
#pragma unroll
            for (int nb = 0; nb < 2; nb++)
#pragma unroll
                for (int ns = 0; ns < 2; ns++)
                    mma_bf16(acc[mf][nb*2 + ns], AH[mf], BL[nb][ns*2], BL[nb][ns*2+1]);
#pragma unroll
        for (int mf = 0; mf < 2; mf++)
#pragma unroll
            for (int nb = 0; nb < 2; nb++)
#pragma unroll
                for (int ns = 0; ns < 2; ns++)
                    mma_bf16(acc[mf][nb*2 + ns], AL[mf], BH[nb][ns*2], BH[nb][ns*2+1]);
    };

    loadA(0, 0); loadB(0, 0); cp_commit();
    cp_wait0(); __syncthreads();

    for (int c = 0; c < 64; c++) {
        const int cur = c & 1, nxt = cur ^ 1;
        if (c < 63) { loadA(c+1, nxt); loadB(c+1, nxt); cp_commit(); }
        mma_step(cur, 0);
        mma_step(cur, 1);
        if (c < 63) { cp_wait0(); }
        __syncthreads();
    }

#pragma unroll
    for (int mf = 0; mf < 2; mf++)
#pragma unroll
        for (int nf = 0; nf < 4; nf++) {
            const float* cc = acc[mf][nf];
            int i = i0 + wm*32 + mf*16 + (l >> 2);
            int c = c0t + wn*32 + nf*8 + (l & 3)*2;
            size_t o1 = ((size_t)bk*NQ + i)*DQ + c;
            size_t o2 = o1 + (size_t)8*DQ;
            __nv_bfloat162 h2, l2;
            h2.x = __float2bfloat16(cc[0]); h2.y = __float2bfloat16(cc[1]);
            l2.x = __float2bfloat16(cc[0] - __bfloat162float(h2.x));
            l2.y = __float2bfloat16(cc[1] - __bfloat162float(h2.y));
            *(__nv_bfloat162*)(g_fh + o1) = h2;
            *(__nv_bfloat162*)(g_fl + o1) = l2;
            h2.x = __float2bfloat16(cc[2]); h2.y = __float2bfloat16(cc[3]);
            l2.x = __float2bfloat16(cc[2] - __bfloat162float(h2.x));
            l2.y = __float2bfloat16(cc[3] - __bfloat162float(h2.y));
            *(__nv_bfloat162*)(g_fh + o2) = h2;
            *(__nv_bfloat162*)(g_fl + o2) = l2;
        }
}

// ---------------------------------------------------------------------------
// Kernel OUT (256 thr, 64-row i-tile): out = LN(sum_k T[b,ksrc(k)] @ Mk[k]^T)
// ---------------------------------------------------------------------------
__global__ __launch_bounds__(256, 1) void out_mma_kernel(
    const float* __restrict__ lbw,
    const float* __restrict__ gammaP, const float* __restrict__ betaP,
    float* __restrict__ out)
{
    extern __shared__ char smc[];
    const unsigned sb = smem_u32(smc);
    const int t = threadIdx.x, l = t & 31, w = t >> 5;
    const int i0 = blockIdx.x * 64;
    const int b  = blockIdx.y;

    int ksrcA[4];
    {
        const float nc0 = -1.0f/(2.0f*__expf(lbw[0]) + 1e-8f);
        ksrcA[0] = 0;
#pragma unroll
        for (int k = 1; k < 4; k++) {
            float nck = -1.0f/(2.0f*__expf(lbw[k]) + 1e-8f);
            ksrcA[k] = (nck == nc0) ? 0 : k;
        }
    }

    float* rowSum = (float*)(smc + CM_LN);
    float* rowSq  = rowSum + 2048;
    float* gammaS = (float*)(smc + CM_GB);
    float* betaS  = gammaS + 512;
    __shared__ float meanS[64], rsS[64];

    for (int u = t; u < 512; u += 256) { gammaS[u] = gammaP[u]; betaS[u] = betaP[u]; }

    float acc[4][8][4];
#pragma unroll
    for (int mf = 0; mf < 4; mf++)
#pragma unroll
        for (int nf = 0; nf < 8; nf++)
#pragma unroll
            for (int q = 0; q < 4; q++) acc[mf][nf][q] = 0.0f;

    auto loadA = [&](int cc, int buf) {
        int row = t >> 2, s = t & 3, sel = s >> 1, h = s & 1;
        int kk = ksrcA[cc >> 5], c512 = (cc & 31)*16;
        const __nv_bfloat16* src = (sel ? g_fl : g_fh) +
            ((size_t)(b*KQ + kk)*NQ + i0 + row)*DQ + c512 + h*8;
        cp16(sb + CM_A + buf*4096 + sw64row(row, sel*32 + h*16), src);
    };
    auto loadB = [&](int cc, int buf) {
        unsigned dst = sb + CM_B + buf*32768;
        int kslot = cc >> 5, c512 = (cc & 31)*16;
#pragma unroll
        for (int rr = 0; rr < 2; rr++) {
            int row = t*2 + rr;
            const __nv_bfloat16* srcH = g_mkh + ((size_t)kslot*512 + row)*512 + c512;
            const __nv_bfloat16* srcL = g_mkl + ((size_t)kslot*512 + row)*512 + c512;
            cp16(dst + sw64row(row, 0),  srcH);
            cp16(dst + sw64row(row, 16), srcH + 8);
            cp16(dst + sw64row(row, 32), srcL);
            cp16(dst + sw64row(row, 48), srcL + 8);
        }
    };

    const unsigned aRow = (unsigned)(l & 15);
    const unsigned aH   = (unsigned)((l >> 4)*16);
    const unsigned bRow = (unsigned)((l & 7) + ((l >> 4) & 1)*8);
    const unsigned bH   = (unsigned)(((l >> 3) & 1)*16);

    loadA(0, 0); loadB(0, 0); cp_commit();
    cp_wait0(); __syncthreads();

    for (int c = 0; c < 128; c++) {
        const int cur = c & 1, nxt = cur ^ 1;
        if (c + 1 < 128) { loadA(c+1, nxt); loadB(c+1, nxt); }
        cp_commit();

        const unsigned abase = sb + CM_A + cur*4096;
        const unsigned bbase = sb + CM_B + cur*32768;
        uint32_t AH[4][4], AL[4][4];
#pragma unroll
        for (int mf = 0; mf < 4; mf++) {
            unsigned r = mf*16 + aRow;
            ldmx4(AH[mf], abase + sw64row(r, aH));
            ldmx4(AL[mf], abase + sw64row(r, 32 + aH));
        }
#pragma unroll
        for (int nb = 0; nb < 4; nb++) {
            uint32_t BH[4], BL[4];
            unsigned r = w*64 + nb*16 + bRow;
            ldmx4(BH, bbase + sw64row(r, bH));
            ldmx4(BL, bbase + sw64row(r, 32 + bH));
#pragma unroll
            for (int mf = 0; mf < 4; mf++)
#pragma unroll
                for (int ns = 0; ns < 2; ns++)
                    mma_bf16(acc[mf][nb*2 + ns], AH[mf], BH[ns*2], BH[ns*2+1]);
#pragma unroll
            for (int mf = 0; mf < 4; mf++)
#pragma unroll
                for (int ns = 0; ns < 2; ns++)
                    mma_bf16(acc[mf][nb*2 + ns], AH[mf], BL[ns*2], BL[ns*2+1]);
#pragma unroll
            for (int mf = 0; mf < 4; mf++)
#pragma unroll
                for (int ns = 0; ns < 2; ns++)
                    mma_bf16(acc[mf][nb*2 + ns], AL[mf], BH[ns*2], BH[ns*2+1]);
        }

        if (c + 1 < 128) { cp_wait0(); }
        __syncthreads();
    }

    const int cw = w*4 + (l & 3);
#pragma unroll
    for (int mf = 0; mf < 4; mf++) {
        float sLo = 0.f, sHi = 0.f, qLo = 0.f, qHi = 0.f;
#pragma unroll
        for (int nf = 0; nf < 8; nf++) {
            const float* cc = acc[mf][nf];
            sLo += cc[0] + cc[1];  qLo += cc[0]*cc[0] + cc[1]*cc[1];
            sHi += cc[2] + cc[3];  qHi += cc[2]*cc[2] + cc[3]*cc[3];
        }
        int rLo = mf*16 + (l >> 2), rHi = rLo + 8;
        rowSum[rLo*32 + cw] = sLo;  rowSq[rLo*32 + cw] = qLo;
        rowSum[rHi*32 + cw] = sHi;  rowSq[rHi*32 + cw] = qHi;
    }
    __syncthreads();
#pragma unroll
    for (int rr = 0; rr < 8; rr++) {
        int row = w*8 + rr;
        float s  = rowSum[row*32 + l];
        float s2 = rowSq [row*32 + l];
#pragma unroll
        for (int off = 16; off > 0; off >>= 1) {
            s  += __shfl_xor_sync(0xffffffffu, s,  off);
            s2 += __shfl_xor_sync(0xffffffffu, s2, off);
        }
        if (l == 0) {
            float mean = s * (1.0f/512.0f);
            float var  = s2 * (1.0f/512.0f) - mean*mean;
            meanS[row] = mean;
            rsS[row]   = rsqrtf(var + 1e-5f);
        }
    }
    __syncthreads();

#pragma unroll
    for (int mf = 0; mf < 4; mf++)
#pragma unroll
        for (int nf = 0; nf < 8; nf++) {
            const float* cc = acc[mf][nf];
            int dout = w*64 + nf*8 + (l & 3)*2;
            float g0 = gammaS[dout], g1 = gammaS[dout+1];
            float b0 = betaS[dout],  b1 = betaS[dout+1];
            int rLo = mf*16 + (l >> 2), rHi = rLo + 8;
            float mLo = meanS[rLo], rsLo = rsS[rLo];
            float mHi = meanS[rHi], rsHi = rsS[rHi];
            float* dLo = out + ((size_t)b*NQ + i0 + rLo)*DQ + dout;
            float* dHi = out + ((size_t)b*NQ + i0 + rHi)*DQ + dout;
            *(float2*)dLo = make_float2((cc[0]-mLo)*rsLo*g0 + b0,
                                        (cc[1]-mLo)*rsLo*g1 + b1);
            *(float2*)dHi = make_float2((cc[2]-mHi)*rsHi*g0 + b0,
                                        (cc[3]-mHi)*rsHi*g1 + b1);
        }
}

// ---------------------------------------------------------------------------
extern "C" void kernel_launch(void* const* d_in, const int* in_sizes, int n_in,
                              void* d_out, int out_size)
{
    const float* charge   = (const float*)d_in[0];
    const float* position = (const float*)d_in[1];
    const float* mass     = (const float*)d_in[2];
    const float* lbw      = (const float*)d_in[3];
    const float* Wch      = (const float*)d_in[4];
    const float* Wcb      = (const float*)d_in[5];
    const float* gammaP   = (const float*)d_in[6];
    const float* betaP    = (const float*)d_in[7];
    float* out = (float*)d_out;

    static cudaStream_t s1 = nullptr;
    static cudaEvent_t evFork = nullptr, evJoin = nullptr;
    if (!s1) {
        cudaStreamCreateWithFlags(&s1, cudaStreamNonBlocking);
        cudaEventCreateWithFlags(&evFork, cudaEventDisableTiming);
        cudaEventCreateWithFlags(&evJoin, cudaEventDisableTiming);
        cudaFuncSetAttribute(mk_build_kernel,
                             cudaFuncAttributeMaxDynamicSharedMemorySize, SMEM_FG);
        cudaFuncSetAttribute(t_gemm_kernel,
                             cudaFuncAttributeMaxDynamicSharedMemorySize, SMEM_FG);
        cudaFuncSetAttribute(out_mma_kernel,
                             cudaFuncAttributeMaxDynamicSharedMemorySize, SMEM_COMB);
    }

    // Fork: side stream builds Mk (from Wcb,Wch) and W (from position,lbw)
    cudaEventRecord(evFork, 0);
    cudaStreamWaitEvent(s1, evFork, 0);
    split_cb_kernel  <<<(DQ*KDQ)/1024, 256, 0, s1>>>(Wcb);
    split_cwt_kernel <<<dim3(KDQ/32, DQ/32), 256, 0, s1>>>(Wch);
    mk_build_kernel  <<<dim3(4, 4, KQ), 512, SMEM_FG, s1>>>();
    wgen_kernel      <<<dim3(NQ/128, NQ/128, BQ), 256, 0, s1>>>(position, lbw);
    cudaEventRecord(evJoin, s1);

    // Main chain: mass*charge transpose-split, then T, then OUT
    split_mct_kernel <<<dim3(NQ/32, DQ/32, BQ), 256>>>(charge, mass);
    cudaStreamWaitEvent(0, evJoin, 0);
    t_gemm_kernel    <<<dim3(NQ/128, DQ/128, BQ*KQ), 512, SMEM_FG>>>(lbw);
    out_mma_kernel   <<<dim3(NQ/64, BQ), 256, SMEM_COMB>>>(lbw, gammaP, betaP, out);
}